// round 9
// baseline (speedup 1.0000x reference)
#include <cuda_runtime.h>
#include <cuda_fp16.h>

#define NBX 168
#define NBY 480
#define NBL 6
#define NBXP (NBX + 4)                // x-padded rows (+2 guard each side)
#define NBYP 496                      // padded y stride in halfs
#define PADY 8                        // y guard offset
#define PLANE (NBXP * NBYP)           // 85312
#define NDEM (NBL * PLANE)            // 511872
#define NREP 4                        // fp16 accumulation replicas
#define QROW (NBYP / 4)               // 124
#define NQ (PLANE / 4)                // 21328
#define WW 5
#define LMAX 1000000
#define INV_SQRT2 0.70710678118654752440f
#define INV_CAP (1.0f / 16.0f)

// Demand: fp16, 4 replicas x 2 shift variants (A slot h; B[h] = A[h+4]).
__device__ __align__(16) __half g_demA[NREP][NDEM];
__device__ __align__(16) __half g_demB[NREP][NDEM];
// Compat: fp16, variant A at [0], variant B at [NDEM].
__device__ __align__(16) __half g_compat2[2 * NDEM];
// Per-instance caches (all range-masked):
__device__ __align__(16) uint4 g_wys[LMAX];  // area*wy, 8 halfs (scatter)
__device__ __align__(16) uint4 g_wyv[LMAX];  // wy, 8 halfs (gather)
__device__ __align__(16) uint4 g_wxv[LMAX];  // wx 5 halfs, pad, map offset

__device__ __forceinline__ void red_add_v4h2(__half* addr, __half2 a, __half2 b,
                                             __half2 c, __half2 d) {
    unsigned ua = *(unsigned*)&a, ub = *(unsigned*)&b;
    unsigned uc = *(unsigned*)&c, ud = *(unsigned*)&d;
    asm volatile("red.global.add.noftz.v4.f16x2 [%0], {%1, %2, %3, %4};"
                 :: "l"(addr), "r"(ua), "r"(ub), "r"(uc), "r"(ud) : "memory");
}

// Fast erf (Abramowitz-Stegun 7.1.26, |abs err| <= 1.5e-7).
__device__ __forceinline__ float erf_fast(float x) {
    float ax = fabsf(x);
    float t = __fdividef(1.0f, fmaf(0.3275911f, ax, 1.0f));
    float e = __expf(-ax * ax);
    float q = fmaf(1.061405429f, t, -1.453152027f);
    q = fmaf(q, t, 1.421413741f);
    q = fmaf(q, t, -0.284496736f);
    q = fmaf(q, t, 0.254829592f);
    float r = fmaf(-q * t, e, 1.0f);
    return copysignf(r, x);
}

__device__ __forceinline__ void wx5(float c, int& b0, float* g) {
    b0 = (int)floorf(c) - 2;
    float ep = erf_fast(((float)b0 - c) * INV_SQRT2);
#pragma unroll
    for (int k = 0; k < WW; k++) {
        float e = erf_fast(((float)(b0 + k + 1) - c) * INV_SQRT2);
        g[k] = 0.5f * (e - ep);
        ep = e;
    }
}

__device__ __forceinline__ void wy8(float c, int& y4, float* w) {
    int b0 = (int)floorf(c) - 2;
    y4 = b0 & ~3;
    int m = b0 - y4;                  // 0..3
    float ep = erf_fast(((float)y4 - c) * INV_SQRT2);
#pragma unroll
    for (int s = 0; s < 8; s++) {
        float e = erf_fast(((float)(y4 + s + 1) - c) * INV_SQRT2);
        bool ok = ((unsigned)(s - m) <= 4u);
        w[s] = ok ? 0.5f * (e - ep) : 0.0f;
        ep = e;
    }
}

// Extract half #i (0..4) from the low 3 words of a uint4 holding packed halfs.
__device__ __forceinline__ float pick_wx(uint4 xv, int i) {
    unsigned sel = (i < 2) ? xv.x : (i < 4) ? xv.y : xv.z;
    unsigned sh = (i & 1) ? (sel >> 16) : (sel & 0xffffu);
    return __half2float(__ushort_as_half((unsigned short)sh));
}

// ---------------------------------------------------------------------------
// Phase 0: compute range-masked weights + offsets once; zero the output.
// ---------------------------------------------------------------------------
__global__ void weights_kernel(const float* __restrict__ pos,
                               const float* __restrict__ nsx,
                               const float* __restrict__ nsy,
                               const int*   __restrict__ lidx,
                               const int*   __restrict__ ltype,
                               float* __restrict__ out, int osz,
                               int Lnum, int n) {
    int l = blockIdx.x * blockDim.x + threadIdx.x;
    int nt = gridDim.x * blockDim.x;
    for (int i = l; i * 2 + 1 < osz; i += nt)
        ((float2*)out)[i] = make_float2(0.0f, 0.0f);
    if (l == 0 && (osz & 1)) out[osz - 1] = 0.0f;
    if (l >= Lnum) return;

    int idx = lidx[l];
    float sx = nsx[idx];
    float sy = nsy[idx];
    float cx = pos[idx]     + 0.5f * sx;
    float cy = pos[n + idx] + 0.5f * sy;
    float area = sx * sy;
    int lt = ltype[idx];

    int bx0, y4;
    float wx[WW], wy[8];
    wx5(cx, bx0, wx);
    wy8(cy, y4, wy);
    // Range masks (equivalent to reference: OOB contributions never count).
#pragma unroll
    for (int s = 0; s < 8; s++)
        if ((unsigned)(y4 + s) >= (unsigned)NBY) wy[s] = 0.0f;
#pragma unroll
    for (int i = 0; i < WW; i++)
        if ((unsigned)(bx0 + i) >= (unsigned)NBX) wx[i] = 0.0f;

    int var  = (y4 & 4) ? 1 : 0;
    int slot = y4 - 4 * var;
    unsigned rowoff = (unsigned)((lt * NBXP + bx0 + 2) * NBYP + PADY + slot);

    uint4 ys, yv, xv;
    __half2 h;
    h = __floats2half2_rn(area * wy[0], area * wy[1]); ys.x = *(unsigned*)&h;
    h = __floats2half2_rn(area * wy[2], area * wy[3]); ys.y = *(unsigned*)&h;
    h = __floats2half2_rn(area * wy[4], area * wy[5]); ys.z = *(unsigned*)&h;
    h = __floats2half2_rn(area * wy[6], area * wy[7]); ys.w = *(unsigned*)&h;
    h = __floats2half2_rn(wy[0], wy[1]); yv.x = *(unsigned*)&h;
    h = __floats2half2_rn(wy[2], wy[3]); yv.y = *(unsigned*)&h;
    h = __floats2half2_rn(wy[4], wy[5]); yv.z = *(unsigned*)&h;
    h = __floats2half2_rn(wy[6], wy[7]); yv.w = *(unsigned*)&h;
    h = __floats2half2_rn(wx[0], wx[1]); xv.x = *(unsigned*)&h;
    h = __floats2half2_rn(wx[2], wx[3]); xv.y = *(unsigned*)&h;
    h = __floats2half2_rn(wx[4], 0.0f);  xv.z = *(unsigned*)&h;
    xv.w = rowoff + (unsigned)var * (unsigned)NDEM;

    g_wys[l] = ys;
    g_wyv[l] = yv;
    g_wxv[l] = xv;
}

// ---------------------------------------------------------------------------
// Phase 1: cooperative scatter — 6 instances/warp, lanes 0-29; each lane
// issues ONE red.v4.f16x2 for its x-row.
// ---------------------------------------------------------------------------
__global__ void scatter_kernel(int Lnum) {
    int tid = blockIdx.x * blockDim.x + threadIdx.x;
    int lane = tid & 31;
    int g = lane / 5;                 // group 0..5 (6 = idle lanes 30,31)
    int i = lane - g * 5;             // x-row 0..4
    int l = (tid >> 5) * 6 + g;
    if (g >= 6 || l >= Lnum) return;

    uint4 ys = g_wys[l];
    uint4 xv = g_wxv[l];
    unsigned off = xv.w;
    int var = off >= (unsigned)NDEM;
    unsigned rowoff = off - (var ? (unsigned)NDEM : 0u);
    int rep = l & (NREP - 1);
    __half* base = (var ? g_demB[rep] : g_demA[rep]) + rowoff + i * NBYP;

    unsigned sel = (i < 2) ? xv.x : (i < 4) ? xv.y : xv.z;
    unsigned sh = (i & 1) ? (sel >> 16) : (sel & 0xffffu);
    __half2 a2 = __half2half2(__ushort_as_half((unsigned short)sh));

    __half2 y0 = *(__half2*)&ys.x;
    __half2 y1 = *(__half2*)&ys.y;
    __half2 y2 = *(__half2*)&ys.z;
    __half2 y3 = *(__half2*)&ys.w;
    red_add_v4h2(base, __hmul2(a2, y0), __hmul2(a2, y1),
                       __hmul2(a2, y2), __hmul2(a2, y3));
}

// ---------------------------------------------------------------------------
// Phase 2: compat = frac * dem (replicas + shift variants summed in fp32),
// written as fp16 into two shifted copies. One thread per 4-half quad.
// ---------------------------------------------------------------------------
__device__ __forceinline__ float4 acc_quad(float4 a, uint2 v) {
    float2 f0 = __half22float2(*(const __half2*)&v.x);
    float2 f1 = __half22float2(*(const __half2*)&v.y);
    a.x += f0.x; a.y += f0.y; a.z += f1.x; a.w += f1.y;
    return a;
}

__global__ void compat_kernel(const int* __restrict__ frac) {
    int q = blockIdx.x * blockDim.x + threadIdx.x;
    if (q >= NQ) return;
    int qr = q % QROW;

    float4 d[NBL];
#pragma unroll
    for (int l = 0; l < NBL; l++) {
        float4 acc = make_float4(0.f, 0.f, 0.f, 0.f);
#pragma unroll
        for (int r = 0; r < NREP; r++)
            acc = acc_quad(acc, *(const uint2*)&g_demA[r][l * PLANE + q * 4]);
        if (qr > 0) {
#pragma unroll
            for (int r = 0; r < NREP; r++)
                acc = acc_quad(acc, *(const uint2*)&g_demB[r][l * PLANE + (q - 1) * 4]);
        }
        d[l] = acc;
    }

#pragma unroll
    for (int t = 0; t < NBL; t++) {
        float4 s = make_float4(0.f, 0.f, 0.f, 0.f);
#pragma unroll
        for (int l = 0; l < NBL; l++) {
            float f = (float)__ldg(&frac[t * NBL + l]);
            s.x = fmaf(f, d[l].x, s.x);
            s.y = fmaf(f, d[l].y, s.y);
            s.z = fmaf(f, d[l].z, s.z);
            s.w = fmaf(f, d[l].w, s.w);
        }
        __half2 h0 = __floats2half2_rn(s.x, s.y);
        __half2 h1 = __floats2half2_rn(s.z, s.w);
        uint2 o;
        o.x = *(unsigned*)&h0;
        o.y = *(unsigned*)&h1;
        *(uint2*)&g_compat2[t * PLANE + q * 4] = o;
        if (qr > 0)
            *(uint2*)&g_compat2[NDEM + t * PLANE + (q - 1) * 4] = o;
    }
}

// ---------------------------------------------------------------------------
// Phase 3: cooperative gather — lane loads one cell, dots with wy, group of
// 5 lanes shfl-reduces; leader stores. Also zeroes dem for the next replay.
// ---------------------------------------------------------------------------
__global__ void gather_kernel(const int* __restrict__ lidx,
                              float* __restrict__ out, int Lnum) {
    int tid = blockIdx.x * blockDim.x + threadIdx.x;
    int nt = gridDim.x * blockDim.x;
    const int NZ = NREP * NDEM / 4;   // uint2 count per array
    for (int z = tid; z < NZ; z += nt) {
        ((uint2*)g_demA)[z] = make_uint2(0u, 0u);
        ((uint2*)g_demB)[z] = make_uint2(0u, 0u);
    }

    int lane = tid & 31;
    int g = lane / 5;
    int i = lane - g * 5;
    int l = (tid >> 5) * 6 + g;
    bool active = (g < 6) && (l < Lnum);

    float partial = 0.0f;
    int idx = 0;
    if (active) {
        uint4 wv = g_wyv[l];
        uint4 xv = g_wxv[l];
        const __half* p = g_compat2 + xv.w + i * NBYP;
        uint4 v = *(const uint4*)p;

        float2 y01 = __half22float2(*(__half2*)&wv.x);
        float2 y23 = __half22float2(*(__half2*)&wv.y);
        float2 y45 = __half22float2(*(__half2*)&wv.z);
        float2 y67 = __half22float2(*(__half2*)&wv.w);
        float2 c0 = __half22float2(*(__half2*)&v.x);
        float2 c1 = __half22float2(*(__half2*)&v.y);
        float2 c2 = __half22float2(*(__half2*)&v.z);
        float2 c3 = __half22float2(*(__half2*)&v.w);
        float d = c0.x * y01.x + c0.y * y01.y + c1.x * y23.x + c1.y * y23.y
                + c2.x * y45.x + c2.y * y45.y + c3.x * y67.x + c3.y * y67.y;
        partial = pick_wx(xv, i) * d;
        if (i == 0) idx = lidx[l];
    }

    // Sum lanes base..base+4 into the group leader (leaders are lanes 0,5,..,25
    // so srcLane stays < 32 for them; other lanes' sums are unused).
    float s = partial;
    s += __shfl_sync(0xffffffffu, partial, lane + 1);
    s += __shfl_sync(0xffffffffu, partial, lane + 2);
    s += __shfl_sync(0xffffffffu, partial, lane + 3);
    s += __shfl_sync(0xffffffffu, partial, lane + 4);

    if (active && i == 0) out[idx] = s * INV_CAP;
}

// ---------------------------------------------------------------------------
extern "C" void kernel_launch(void* const* d_in, const int* in_sizes, int n_in,
                              void* d_out, int out_size) {
    const float* pos   = (const float*)d_in[0];
    const float* nsx   = (const float*)d_in[1];
    const float* nsy   = (const float*)d_in[2];
    const int*   lidx  = (const int*)d_in[3];
    const int*   ltype = (const int*)d_in[4];
    const int*   frac  = (const int*)d_in[5];
    float* out = (float*)d_out;

    int n    = in_sizes[1];   // number of nodes (2M)
    int Lnum = in_sizes[3];   // number of instances (1M)
    if (Lnum > LMAX) Lnum = LMAX;

    weights_kernel<<<(Lnum + 255) / 256, 256>>>(pos, nsx, nsy, lidx, ltype,
                                                out, out_size, Lnum, n);
    int warps = (Lnum + 5) / 6;
    int cthreads = warps * 32;
    int cblocks = (cthreads + 255) / 256;
    scatter_kernel<<<cblocks, 256>>>(Lnum);
    compat_kernel<<<(NQ + 255) / 256, 256>>>(frac);
    gather_kernel<<<cblocks, 256>>>(lidx, out, Lnum);
}

// round 10
// speedup vs baseline: 1.5175x; 1.5175x over previous
#include <cuda_runtime.h>
#include <cuda_fp16.h>

#define NBX 168
#define NBY 480
#define NBL 6
#define NBXP 172                      // x index range: bx0+2+i in [0,172)
#define NYS 62                        // ys index range (slot/8 + 1) in [0,61]
#define WW 5
#define NREP 4                        // fp16 accumulation replicas
#define CELLS (2 * NBL * NYS * NBXP)  // 127968 cells (var,t,ys,x)
#define NDEM2 (CELLS * 8)             // 1023744 halfs (~2MB)
#define NPLANE (NYS * NBXP)           // 10664
#define INV_SQRT2 0.70710678118654752440f
#define INV_CAP (1.0f / 16.0f)

// Cell (var,t,ys,x) holds 8 halfs covering absolute y = 8*(ys-1)+4*var + k.
#define OFFC(var, t, ys, x) \
    ((((((var) * NBL) + (t)) * NYS + (ys)) * NBXP + (x)) * 8)

__device__ __align__(16) __half g_dem2[NREP][NDEM2];
__device__ __align__(16) __half g_compat2[NDEM2];

__device__ __forceinline__ void red_add_v4h2(__half* addr, __half2 a, __half2 b,
                                             __half2 c, __half2 d) {
    unsigned ua = *(unsigned*)&a, ub = *(unsigned*)&b;
    unsigned uc = *(unsigned*)&c, ud = *(unsigned*)&d;
    asm volatile("red.global.add.noftz.v4.f16x2 [%0], {%1, %2, %3, %4};"
                 :: "l"(addr), "r"(ua), "r"(ub), "r"(uc), "r"(ud) : "memory");
}

// Fast erf (Abramowitz-Stegun 7.1.26, |abs err| <= 1.5e-7).
__device__ __forceinline__ float erf_fast(float x) {
    float ax = fabsf(x);
    float t = __fdividef(1.0f, fmaf(0.3275911f, ax, 1.0f));
    float e = __expf(-ax * ax);
    float q = fmaf(1.061405429f, t, -1.453152027f);
    q = fmaf(q, t, 1.421413741f);
    q = fmaf(q, t, -0.284496736f);
    q = fmaf(q, t, 0.254829592f);
    float r = fmaf(-q * t, e, 1.0f);
    return copysignf(r, x);
}

// 5-wide x-axis weights, no range mask (spill goes to pad cells).
__device__ __forceinline__ void wx5(float c, int& b0, float* g) {
    b0 = (int)floorf(c) - 2;
    float ep = erf_fast(((float)b0 - c) * INV_SQRT2);
#pragma unroll
    for (int k = 0; k < WW; k++) {
        float e = erf_fast(((float)(b0 + k + 1) - c) * INV_SQRT2);
        g[k] = 0.5f * (e - ep);
        ep = e;
    }
}

// 8 slots at 4-aligned y4. Window-truncation mask always; RANGE adds [0,NBY).
template <bool RANGE>
__device__ __forceinline__ void wy8(float c, int& y4, float* w) {
    int b0 = (int)floorf(c) - 2;
    y4 = b0 & ~3;
    int m = b0 - y4;                  // 0..3
    float ep = erf_fast(((float)y4 - c) * INV_SQRT2);
#pragma unroll
    for (int s = 0; s < 8; s++) {
        float e = erf_fast(((float)(y4 + s + 1) - c) * INV_SQRT2);
        bool ok = ((unsigned)(s - m) <= 4u);
        if (RANGE) ok = ok && ((unsigned)(y4 + s) < NBY);
        w[s] = ok ? 0.5f * (e - ep) : 0.0f;
        ep = e;
    }
}

// ---------------------------------------------------------------------------
// Phase 1: scatter — 5 v4.f16x2 REDs per instance, now to CONTIGUOUS 16B
// cells (80B total, 1-2 L2 lines). Also zeroes the output buffer.
// ---------------------------------------------------------------------------
__global__ void scatter_kernel(const float* __restrict__ pos,
                               const float* __restrict__ nsx,
                               const float* __restrict__ nsy,
                               const int*   __restrict__ lidx,
                               const int*   __restrict__ ltype,
                               float* __restrict__ out, int osz,
                               int Lnum, int n) {
    int l = blockIdx.x * blockDim.x + threadIdx.x;
    int nt = gridDim.x * blockDim.x;
    for (int i = l; i * 2 + 1 < osz; i += nt)
        ((float2*)out)[i] = make_float2(0.0f, 0.0f);
    if (l == 0 && (osz & 1)) out[osz - 1] = 0.0f;

    if (l >= Lnum) return;
    int idx = lidx[l];
    float sx = nsx[idx];
    float sy = nsy[idx];
    float cx = pos[idx]     + 0.5f * sx;
    float cy = pos[n + idx] + 0.5f * sy;
    float area = sx * sy;
    int lt = ltype[idx];
    int rep = l & (NREP - 1);

    int bx0, y4;
    float wx[WW], wy[8];
    wx5(cx, bx0, wx);
    wy8<false>(cy, y4, wy);

    __half2 hwy[4];
    hwy[0] = __floats2half2_rn(wy[0], wy[1]);
    hwy[1] = __floats2half2_rn(wy[2], wy[3]);
    hwy[2] = __floats2half2_rn(wy[4], wy[5]);
    hwy[3] = __floats2half2_rn(wy[6], wy[7]);

    int var   = (y4 >> 2) & 1;
    int slot  = y4 - 4 * var;         // multiple of 8, may be -8
    int ysIdx = slot / 8 + 1;         // [0, 60]
    __half* base = g_dem2[rep] + OFFC(var, lt, ysIdx, bx0 + 2);

#pragma unroll
    for (int i = 0; i < WW; i++) {
        __half2 a2 = __half2half2(__float2half_rn(area * wx[i]));
        red_add_v4h2(base + i * 8,
                     __hmul2(a2, hwy[0]), __hmul2(a2, hwy[1]),
                     __hmul2(a2, hwy[2]), __hmul2(a2, hwy[3]));
    }
}

// ---------------------------------------------------------------------------
// Phase 2: compat. Thread per (ys, x): reconstruct absolute-y demand for
// y = 8*(ys-1)+k (k=0..7) from A/B cells of all replicas, matvec with frac,
// store A cell (full 16B), B[ys] halfs 0-3, B[ys-1] halfs 4-7.
// ---------------------------------------------------------------------------
__device__ __forceinline__ void acc8(float* d, uint4 v, int shift) {
    // add the 8 halfs of v into d[shift..shift+7] conceptually; here shift
    // selects mapping: 0 -> d[k]+=v[k]
    float2 f;
    f = __half22float2(*(const __half2*)&v.x); d[0] += f.x; d[1] += f.y;
    f = __half22float2(*(const __half2*)&v.y); d[2] += f.x; d[3] += f.y;
    f = __half22float2(*(const __half2*)&v.z); d[4] += f.x; d[5] += f.y;
    f = __half22float2(*(const __half2*)&v.w); d[6] += f.x; d[7] += f.y;
}

__global__ void compat_kernel(const int* __restrict__ frac) {
    int p = blockIdx.x * blockDim.x + threadIdx.x;
    if (p >= NPLANE) return;
    int ysIdx = p / NBXP;
    int x = p - ysIdx * NBXP;

    float ff[NBL][NBL];
#pragma unroll
    for (int t = 0; t < NBL; t++)
#pragma unroll
        for (int l = 0; l < NBL; l++)
            ff[t][l] = (float)__ldg(&frac[t * NBL + l]);

    float s[NBL][8];
#pragma unroll
    for (int t = 0; t < NBL; t++)
#pragma unroll
        for (int k = 0; k < 8; k++) s[t][k] = 0.0f;

#pragma unroll
    for (int l = 0; l < NBL; l++) {
        float d8[8];
#pragma unroll
        for (int k = 0; k < 8; k++) d8[k] = 0.0f;
#pragma unroll
        for (int r = 0; r < NREP; r++) {
            // A (var0) cell at ysIdx: covers y = 8(ys-1)+k directly.
            uint4 va = *(const uint4*)&g_dem2[r][OFFC(0, l, ysIdx, x)];
            acc8(d8, va, 0);
            // B (var1) cell ysIdx: halfs 0-3 -> our k'=4..7.
            uint4 vb = *(const uint4*)&g_dem2[r][OFFC(1, l, ysIdx, x)];
            float2 f;
            f = __half22float2(*(const __half2*)&vb.x); d8[4] += f.x; d8[5] += f.y;
            f = __half22float2(*(const __half2*)&vb.y); d8[6] += f.x; d8[7] += f.y;
            // B cell ysIdx-1: halfs 4-7 -> our k'=0..3.
            if (ysIdx > 0) {
                uint4 vp = *(const uint4*)&g_dem2[r][OFFC(1, l, ysIdx - 1, x)];
                f = __half22float2(*(const __half2*)&vp.z); d8[0] += f.x; d8[1] += f.y;
                f = __half22float2(*(const __half2*)&vp.w); d8[2] += f.x; d8[3] += f.y;
            }
        }
#pragma unroll
        for (int t = 0; t < NBL; t++) {
            float f = ff[t][l];
#pragma unroll
            for (int k = 0; k < 8; k++)
                s[t][k] = fmaf(f, d8[k], s[t][k]);
        }
    }

#pragma unroll
    for (int t = 0; t < NBL; t++) {
        __half2 h0 = __floats2half2_rn(s[t][0], s[t][1]);
        __half2 h1 = __floats2half2_rn(s[t][2], s[t][3]);
        __half2 h2 = __floats2half2_rn(s[t][4], s[t][5]);
        __half2 h3 = __floats2half2_rn(s[t][6], s[t][7]);
        uint4 o;
        o.x = *(unsigned*)&h0; o.y = *(unsigned*)&h1;
        o.z = *(unsigned*)&h2; o.w = *(unsigned*)&h3;
        // A cell: full window.
        *(uint4*)&g_compat2[OFFC(0, t, ysIdx, x)] = o;
        // B cell ysIdx halfs 0-3 <- s[4..7].
        uint2 lo; lo.x = o.z; lo.y = o.w;
        *(uint2*)&g_compat2[OFFC(1, t, ysIdx, x)] = lo;
        // B cell ysIdx-1 halfs 4-7 <- s[0..3].
        if (ysIdx > 0) {
            uint2 hi; hi.x = o.x; hi.y = o.y;
            *(uint2*)&g_compat2[OFFC(1, t, ysIdx - 1, x) + 4] = hi;
        }
    }
}

// ---------------------------------------------------------------------------
// Phase 3: gather — 5 contiguous LDG.128 (rows 1-4 hit L1). Also zeroes the
// demand replicas for the next replay.
// ---------------------------------------------------------------------------
__global__ void gather_kernel(const float* __restrict__ pos,
                              const float* __restrict__ nsx,
                              const float* __restrict__ nsy,
                              const int*   __restrict__ lidx,
                              const int*   __restrict__ ltype,
                              float* __restrict__ out,
                              int Lnum, int n) {
    int l = blockIdx.x * blockDim.x + threadIdx.x;
    int nt = gridDim.x * blockDim.x;
    const int NZ = NREP * NDEM2 / 8;        // uint4 count over g_dem2
    for (int i = l; i < NZ; i += nt)
        ((uint4*)g_dem2)[i] = make_uint4(0u, 0u, 0u, 0u);

    if (l >= Lnum) return;
    int idx = lidx[l];
    float sx = nsx[idx];
    float sy = nsy[idx];
    float cx = pos[idx]     + 0.5f * sx;
    float cy = pos[n + idx] + 0.5f * sy;
    int lt = ltype[idx];

    int bx0, y4;
    float wx[WW], wy[8];
    wx5(cx, bx0, wx);
    wy8<true>(cy, y4, wy);
#pragma unroll
    for (int i = 0; i < WW; i++)
        if ((unsigned)(bx0 + i) >= (unsigned)NBX) wx[i] = 0.0f;

    int var   = (y4 >> 2) & 1;
    int slot  = y4 - 4 * var;
    int ysIdx = slot / 8 + 1;
    const __half* base = g_compat2 + OFFC(var, lt, ysIdx, bx0 + 2);

    uint4 v[WW];
#pragma unroll
    for (int i = 0; i < WW; i++)
        v[i] = *(const uint4*)(base + i * 8);

    float s = 0.0f;
#pragma unroll
    for (int i = 0; i < WW; i++) {
        float2 c0 = __half22float2(*(const __half2*)&v[i].x);
        float2 c1 = __half22float2(*(const __half2*)&v[i].y);
        float2 c2 = __half22float2(*(const __half2*)&v[i].z);
        float2 c3 = __half22float2(*(const __half2*)&v[i].w);
        float sj = c0.x * wy[0] + c0.y * wy[1] + c1.x * wy[2] + c1.y * wy[3]
                 + c2.x * wy[4] + c2.y * wy[5] + c3.x * wy[6] + c3.y * wy[7];
        s += wx[i] * sj;
    }
    out[idx] = s * INV_CAP;
}

// ---------------------------------------------------------------------------
extern "C" void kernel_launch(void* const* d_in, const int* in_sizes, int n_in,
                              void* d_out, int out_size) {
    const float* pos   = (const float*)d_in[0];
    const float* nsx   = (const float*)d_in[1];
    const float* nsy   = (const float*)d_in[2];
    const int*   lidx  = (const int*)d_in[3];
    const int*   ltype = (const int*)d_in[4];
    const int*   frac  = (const int*)d_in[5];
    float* out = (float*)d_out;

    int n    = in_sizes[1];   // number of nodes (2M)
    int Lnum = in_sizes[3];   // number of instances (1M)

    scatter_kernel<<<(Lnum + 255) / 256, 256>>>(pos, nsx, nsy, lidx, ltype,
                                                out, out_size, Lnum, n);
    compat_kernel<<<(NPLANE + 255) / 256, 256>>>(frac);
    gather_kernel<<<(Lnum + 255) / 256, 256>>>(pos, nsx, nsy, lidx, ltype,
                                               out, Lnum, n);
}

// round 11
// speedup vs baseline: 1.5569x; 1.0260x over previous
#include <cuda_runtime.h>
#include <cuda_fp16.h>

#define NBX 168
#define NBY 480
#define NBL 6
#define NBXP 172                      // x index range: bx0+2+i in [0,172)
#define NYS 62                        // ys index range (slot/8 + 1) in [0,61]
#define WW 5
#define NREP 2                        // fp16 accumulation replicas
#define CELLS (2 * NBL * NYS * NBXP)  // 127968 cells (var,t,ys,x)
#define NDEM2 (CELLS * 8)             // 1023744 halfs (~2MB)
#define NPLANE (NYS * NBXP)           // 10664
#define INV_SQRT2 0.70710678118654752440f
#define INV_CAP (1.0f / 16.0f)

// Cell (var,t,ys,x) holds 8 halfs covering absolute y = 8*(ys-1)+4*var + k.
#define OFFC(var, t, ys, x) \
    ((((((var) * NBL) + (t)) * NYS + (ys)) * NBXP + (x)) * 8)

__device__ __align__(16) __half g_dem2[NREP][NDEM2];
__device__ __align__(16) __half g_compat2[NDEM2];

__device__ __forceinline__ void red_add_v4h2(__half* addr, __half2 a, __half2 b,
                                             __half2 c, __half2 d) {
    unsigned ua = *(unsigned*)&a, ub = *(unsigned*)&b;
    unsigned uc = *(unsigned*)&c, ud = *(unsigned*)&d;
    asm volatile("red.global.add.noftz.v4.f16x2 [%0], {%1, %2, %3, %4};"
                 :: "l"(addr), "r"(ua), "r"(ub), "r"(uc), "r"(ud) : "memory");
}

// Fast erf (Abramowitz-Stegun 7.1.26, |abs err| <= 1.5e-7).
__device__ __forceinline__ float erf_fast(float x) {
    float ax = fabsf(x);
    float t = __fdividef(1.0f, fmaf(0.3275911f, ax, 1.0f));
    float e = __expf(-ax * ax);
    float q = fmaf(1.061405429f, t, -1.453152027f);
    q = fmaf(q, t, 1.421413741f);
    q = fmaf(q, t, -0.284496736f);
    q = fmaf(q, t, 0.254829592f);
    float r = fmaf(-q * t, e, 1.0f);
    return copysignf(r, x);
}

// 5-wide x-axis weights, no range mask (spill goes to pad cells).
__device__ __forceinline__ void wx5(float c, int& b0, float* g) {
    b0 = (int)floorf(c) - 2;
    float ep = erf_fast(((float)b0 - c) * INV_SQRT2);
#pragma unroll
    for (int k = 0; k < WW; k++) {
        float e = erf_fast(((float)(b0 + k + 1) - c) * INV_SQRT2);
        g[k] = 0.5f * (e - ep);
        ep = e;
    }
}

// 8 slots at 4-aligned y4. Window-truncation mask always; RANGE adds [0,NBY).
template <bool RANGE>
__device__ __forceinline__ void wy8(float c, int& y4, float* w) {
    int b0 = (int)floorf(c) - 2;
    y4 = b0 & ~3;
    int m = b0 - y4;                  // 0..3
    float ep = erf_fast(((float)y4 - c) * INV_SQRT2);
#pragma unroll
    for (int s = 0; s < 8; s++) {
        float e = erf_fast(((float)(y4 + s + 1) - c) * INV_SQRT2);
        bool ok = ((unsigned)(s - m) <= 4u);
        if (RANGE) ok = ok && ((unsigned)(y4 + s) < NBY);
        w[s] = ok ? 0.5f * (e - ep) : 0.0f;
        ep = e;
    }
}

// ---------------------------------------------------------------------------
// Phase 1: scatter — 5 v4.f16x2 REDs per instance to contiguous 16B cells.
// ---------------------------------------------------------------------------
__global__ void scatter_kernel(const float* __restrict__ pos,
                               const float* __restrict__ nsx,
                               const float* __restrict__ nsy,
                               const int*   __restrict__ lidx,
                               const int*   __restrict__ ltype,
                               int Lnum, int n) {
    int l = blockIdx.x * blockDim.x + threadIdx.x;
    if (l >= Lnum) return;
    int idx = lidx[l];
    float sx = nsx[idx];
    float sy = nsy[idx];
    float cx = pos[idx]     + 0.5f * sx;
    float cy = pos[n + idx] + 0.5f * sy;
    float area = sx * sy;
    int lt = ltype[idx];
    int rep = l & (NREP - 1);

    int bx0, y4;
    float wx[WW], wy[8];
    wx5(cx, bx0, wx);
    wy8<false>(cy, y4, wy);

    __half2 hwy[4];
    hwy[0] = __floats2half2_rn(wy[0], wy[1]);
    hwy[1] = __floats2half2_rn(wy[2], wy[3]);
    hwy[2] = __floats2half2_rn(wy[4], wy[5]);
    hwy[3] = __floats2half2_rn(wy[6], wy[7]);

    int var   = (y4 >> 2) & 1;
    int slot  = y4 - 4 * var;         // multiple of 8, may be -8
    int ysIdx = slot / 8 + 1;         // [0, 60]
    __half* base = g_dem2[rep] + OFFC(var, lt, ysIdx, bx0 + 2);

#pragma unroll
    for (int i = 0; i < WW; i++) {
        __half2 a2 = __half2half2(__float2half_rn(area * wx[i]));
        red_add_v4h2(base + i * 8,
                     __hmul2(a2, hwy[0]), __hmul2(a2, hwy[1]),
                     __hmul2(a2, hwy[2]), __hmul2(a2, hwy[3]));
    }
}

// ---------------------------------------------------------------------------
// Phase 2: compat (thread per (ys,x) for p < NPLANE) + output zeroing spread
// across the whole (wide) grid. Compat threads also zero the A-cells they
// exclusively read (re-arming them for the next replay).
// ---------------------------------------------------------------------------
__global__ void compat_kernel(const int* __restrict__ frac,
                              float* __restrict__ out, int osz) {
    int p = blockIdx.x * blockDim.x + threadIdx.x;
    int nt = gridDim.x * blockDim.x;
    // Zero the output buffer (gather overwrites touched entries later).
    for (int i = p; i * 2 + 1 < osz; i += nt)
        ((float2*)out)[i] = make_float2(0.0f, 0.0f);
    if (p == 0 && (osz & 1)) out[osz - 1] = 0.0f;

    if (p >= NPLANE) return;
    int ysIdx = p / NBXP;
    int x = p - ysIdx * NBXP;

    float ff[NBL][NBL];
#pragma unroll
    for (int t = 0; t < NBL; t++)
#pragma unroll
        for (int l = 0; l < NBL; l++)
            ff[t][l] = (float)__ldg(&frac[t * NBL + l]);

    float s[NBL][8];
#pragma unroll
    for (int t = 0; t < NBL; t++)
#pragma unroll
        for (int k = 0; k < 8; k++) s[t][k] = 0.0f;

    const uint4 zero4 = make_uint4(0u, 0u, 0u, 0u);

#pragma unroll
    for (int l = 0; l < NBL; l++) {
        float d8[8];
#pragma unroll
        for (int k = 0; k < 8; k++) d8[k] = 0.0f;
#pragma unroll
        for (int r = 0; r < NREP; r++) {
            // A (var0) cell at ysIdx: covers y = 8(ys-1)+k directly.
            // Read it, then re-zero it for the next replay (sole reader).
            uint4 va = *(const uint4*)&g_dem2[r][OFFC(0, l, ysIdx, x)];
            *(uint4*)&g_dem2[r][OFFC(0, l, ysIdx, x)] = zero4;
            float2 f;
            f = __half22float2(*(const __half2*)&va.x); d8[0] += f.x; d8[1] += f.y;
            f = __half22float2(*(const __half2*)&va.y); d8[2] += f.x; d8[3] += f.y;
            f = __half22float2(*(const __half2*)&va.z); d8[4] += f.x; d8[5] += f.y;
            f = __half22float2(*(const __half2*)&va.w); d8[6] += f.x; d8[7] += f.y;
            // B (var1) cell ysIdx: halfs 0-3 -> our k'=4..7.
            uint4 vb = *(const uint4*)&g_dem2[r][OFFC(1, l, ysIdx, x)];
            f = __half22float2(*(const __half2*)&vb.x); d8[4] += f.x; d8[5] += f.y;
            f = __half22float2(*(const __half2*)&vb.y); d8[6] += f.x; d8[7] += f.y;
            // B cell ysIdx-1: halfs 4-7 -> our k'=0..3.
            if (ysIdx > 0) {
                uint4 vp = *(const uint4*)&g_dem2[r][OFFC(1, l, ysIdx - 1, x)];
                f = __half22float2(*(const __half2*)&vp.z); d8[0] += f.x; d8[1] += f.y;
                f = __half22float2(*(const __half2*)&vp.w); d8[2] += f.x; d8[3] += f.y;
            }
        }
#pragma unroll
        for (int t = 0; t < NBL; t++) {
            float f = ff[t][l];
#pragma unroll
            for (int k = 0; k < 8; k++)
                s[t][k] = fmaf(f, d8[k], s[t][k]);
        }
    }

#pragma unroll
    for (int t = 0; t < NBL; t++) {
        __half2 h0 = __floats2half2_rn(s[t][0], s[t][1]);
        __half2 h1 = __floats2half2_rn(s[t][2], s[t][3]);
        __half2 h2 = __floats2half2_rn(s[t][4], s[t][5]);
        __half2 h3 = __floats2half2_rn(s[t][6], s[t][7]);
        uint4 o;
        o.x = *(unsigned*)&h0; o.y = *(unsigned*)&h1;
        o.z = *(unsigned*)&h2; o.w = *(unsigned*)&h3;
        // A cell: full window.
        *(uint4*)&g_compat2[OFFC(0, t, ysIdx, x)] = o;
        // B cell ysIdx halfs 0-3 <- s[4..7].
        uint2 lo; lo.x = o.z; lo.y = o.w;
        *(uint2*)&g_compat2[OFFC(1, t, ysIdx, x)] = lo;
        // B cell ysIdx-1 halfs 4-7 <- s[0..3].
        if (ysIdx > 0) {
            uint2 hi; hi.x = o.x; hi.y = o.y;
            *(uint2*)&g_compat2[OFFC(1, t, ysIdx - 1, x) + 4] = hi;
        }
    }
}

// ---------------------------------------------------------------------------
// Phase 3: gather — 5 contiguous LDG.128 + dot. Zeroes only the B-cells of
// the demand maps (A-cells were re-armed inside compat).
// ---------------------------------------------------------------------------
__global__ void gather_kernel(const float* __restrict__ pos,
                              const float* __restrict__ nsx,
                              const float* __restrict__ nsy,
                              const int*   __restrict__ lidx,
                              const int*   __restrict__ ltype,
                              float* __restrict__ out,
                              int Lnum, int n) {
    int l = blockIdx.x * blockDim.x + threadIdx.x;
    int nt = gridDim.x * blockDim.x;
    // Zero B-cell halves of each replica (second half of each map).
    const int NZB = (NDEM2 / 2) / 8;        // uint4 count per replica B-region
    for (int i = l; i < NREP * NZB; i += nt) {
        int r = i / NZB;
        int j = i - r * NZB;
        ((uint4*)(g_dem2[r] + NDEM2 / 2))[j] = make_uint4(0u, 0u, 0u, 0u);
    }

    if (l >= Lnum) return;
    int idx = lidx[l];
    float sx = nsx[idx];
    float sy = nsy[idx];
    float cx = pos[idx]     + 0.5f * sx;
    float cy = pos[n + idx] + 0.5f * sy;
    int lt = ltype[idx];

    int bx0, y4;
    float wx[WW], wy[8];
    wx5(cx, bx0, wx);
    wy8<true>(cy, y4, wy);
#pragma unroll
    for (int i = 0; i < WW; i++)
        if ((unsigned)(bx0 + i) >= (unsigned)NBX) wx[i] = 0.0f;

    int var   = (y4 >> 2) & 1;
    int slot  = y4 - 4 * var;
    int ysIdx = slot / 8 + 1;
    const __half* base = g_compat2 + OFFC(var, lt, ysIdx, bx0 + 2);

    uint4 v[WW];
#pragma unroll
    for (int i = 0; i < WW; i++)
        v[i] = *(const uint4*)(base + i * 8);

    float s = 0.0f;
#pragma unroll
    for (int i = 0; i < WW; i++) {
        float2 c0 = __half22float2(*(const __half2*)&v[i].x);
        float2 c1 = __half22float2(*(const __half2*)&v[i].y);
        float2 c2 = __half22float2(*(const __half2*)&v[i].z);
        float2 c3 = __half22float2(*(const __half2*)&v[i].w);
        float sj = c0.x * wy[0] + c0.y * wy[1] + c1.x * wy[2] + c1.y * wy[3]
                 + c2.x * wy[4] + c2.y * wy[5] + c3.x * wy[6] + c3.y * wy[7];
        s += wx[i] * sj;
    }
    out[idx] = s * INV_CAP;
}

// ---------------------------------------------------------------------------
extern "C" void kernel_launch(void* const* d_in, const int* in_sizes, int n_in,
                              void* d_out, int out_size) {
    const float* pos   = (const float*)d_in[0];
    const float* nsx   = (const float*)d_in[1];
    const float* nsy   = (const float*)d_in[2];
    const int*   lidx  = (const int*)d_in[3];
    const int*   ltype = (const int*)d_in[4];
    const int*   frac  = (const int*)d_in[5];
    float* out = (float*)d_out;

    int n    = in_sizes[1];   // number of nodes (2M)
    int Lnum = in_sizes[3];   // number of instances (1M)

    scatter_kernel<<<(Lnum + 255) / 256, 256>>>(pos, nsx, nsy, lidx, ltype,
                                                Lnum, n);
    // Wide grid: cell work for p < NPLANE, out-zeroing spread across all.
    compat_kernel<<<2048, 256>>>(frac, out, out_size);
    gather_kernel<<<(Lnum + 255) / 256, 256>>>(pos, nsx, nsy, lidx, ltype,
                                               out, Lnum, n);
}